// round 2
// baseline (speedup 1.0000x reference)
#include <cuda_runtime.h>

#define GH 96
#define GW 96
#define HW (GH*GW)
#define BSZ 8
#define LN 16
#define PN 16
#define NCELL (BSZ*GH*GW)   /* 73728 */
#define TPB 256
#define NBLK (NCELL/TPB)    /* 288 */

__device__ float g_partials[NBLK];

__device__ __forceinline__ float asqrt(float x) {
    float r;
    asm("sqrt.approx.f32 %0, %1;" : "=f"(r) : "f"(x));
    return r;
}

__global__ __launch_bounds__(TPB, 2)
void yolino_main(const float* __restrict__ target, const float* __restrict__ pred)
{
    const int n = blockIdx.x * TPB + threadIdx.x;   // n in [0, NCELL)
    const int w  = n % GW;
    const int t1 = n / GW;
    const int h  = t1 % GH;
    const int b  = t1 / GH;

    const float* tb = target + (size_t)b * 64 * HW + (size_t)h * GW + w;
    const float* pb = pred   + (size_t)b * 96 * HW + (size_t)h * GW + w;

    // Load all 16 target lines (4 coords each) — coalesced across the warp.
    float tl[LN][4];
    #pragma unroll
    for (int l = 0; l < LN; ++l) {
        #pragma unroll
        for (int j = 0; j < 4; ++j)
            tl[l][j] = tb[(size_t)(l * 4 + j) * HW];
    }

    // Valid-line mask: sum of the 4 coords > 0
    unsigned tmask = 0;
    #pragma unroll
    for (int l = 0; l < LN; ++l) {
        float s = (tl[l][0] + tl[l][1]) + (tl[l][2] + tl[l][3]);
        if (s > 0.f) tmask |= (1u << l);
    }

    float loss = 0.f;

    // Prefetch predictor 0's six channels.
    float q0 = pb[0], q1 = pb[HW], q2 = pb[2 * HW],
          q3 = pb[3 * HW], q4 = pb[4 * HW], q5 = pb[5 * HW];

    #pragma unroll 1
    for (int p = 0; p < PN; ++p) {
        const float c0 = q0, c1 = q1, c2 = q2, c3 = q3, c4 = q4, c5 = q5;

        // Prefetch next predictor while we crunch this one.
        if (p + 1 < PN) {
            const float* nb = pb + (size_t)((p + 1) * 6) * HW;
            q0 = nb[0];      q1 = nb[HW];     q2 = nb[2 * HW];
            q3 = nb[3 * HW]; q4 = nb[4 * HW]; q5 = nb[5 * HW];
        }

        float d[LN];
        float m = 3.4e38f;
        #pragma unroll
        for (int l = 0; l < LN; ++l) {
            float dx1 = tl[l][0] - c0, dy1 = tl[l][1] - c1;
            float dx2 = tl[l][2] - c2, dy2 = tl[l][3] - c3;
            float s1 = fmaf(dx1, dx1, dy1 * dy1);
            float s2 = fmaf(dx2, dx2, dy2 * dy2);
            float dd = asqrt(s1) + asqrt(s2);
            d[l] = dd;
            m = fminf(m, dd);
        }

        const float thr = (m < 2.f) ? m : -1.f;

        float cnt  = 0.f;   // number of l with ijk_mask true for this p
        float dsum = 0.f;   // sum of dist over selected l
        #pragma unroll
        for (int l = 0; l < LN; ++l) {
            bool sel = (d[l] == thr) && ((tmask >> l) & 1u);
            if (sel) { dsum += d[l]; cnt += 1.f; }
        }
        loss += dsum;

        // Confidence term: (sig-1)^2 if any match else sig^2
        float sig = 1.f / (1.f + __expf(-c4));
        float e   = (cnt > 0.f) ? (sig - 1.f) : sig;
        loss = fmaf(e, e, loss);

        // Class term: (1 - cls_hard)^2 summed over selected l.
        // cls_hard = sigmoid(c5) > 0.5  <=>  c5 > 0
        if (!(c5 > 0.f)) loss += cnt;
    }

    // ---- block reduction (deterministic) ----
    #pragma unroll
    for (int o = 16; o > 0; o >>= 1)
        loss += __shfl_xor_sync(0xffffffffu, loss, o);

    __shared__ float sw[TPB / 32];
    const int lane = threadIdx.x & 31;
    const int wid  = threadIdx.x >> 5;
    if (lane == 0) sw[wid] = loss;
    __syncthreads();
    if (wid == 0) {
        float v = (lane < TPB / 32) ? sw[lane] : 0.f;
        #pragma unroll
        for (int o = 4; o > 0; o >>= 1)
            v += __shfl_xor_sync(0xffffffffu, v, o);
        if (lane == 0) g_partials[blockIdx.x] = v;
    }
}

__global__ void yolino_reduce(float* __restrict__ out)
{
    __shared__ float s[256];
    const int t = threadIdx.x;
    float v = g_partials[t];
    if (t + 256 < NBLK) v += g_partials[t + 256];
    s[t] = v;
    __syncthreads();
    #pragma unroll
    for (int o = 128; o > 0; o >>= 1) {
        if (t < o) s[t] += s[t + o];
        __syncthreads();
    }
    if (t == 0) out[0] = s[0] * (1.0f / BSZ);
}

extern "C" void kernel_launch(void* const* d_in, const int* in_sizes, int n_in,
                              void* d_out, int out_size)
{
    const float* target = (const float*)d_in[0];
    const float* pred   = (const float*)d_in[1];
    float* out = (float*)d_out;

    yolino_main<<<NBLK, TPB>>>(target, pred);
    yolino_reduce<<<1, 256>>>(out);
}

// round 3
// speedup vs baseline: 1.0028x; 1.0028x over previous
#include <cuda_runtime.h>

#define GH 96
#define GW 96
#define HW (GH*GW)
#define BSZ 8
#define LN 16
#define PN 16
#define NCELL (BSZ*GH*GW)   /* 73728 */
#define TPB 256
#define NBLK (NCELL/TPB)    /* 288 */

__device__ float g_partials[NBLK];
__device__ unsigned int g_ticket;   // zero-init; last block resets it

typedef unsigned long long u64;

__device__ __forceinline__ float asqrt(float x) {
    float r;
    asm("sqrt.approx.f32 %0, %1;" : "=f"(r) : "f"(x));
    return r;
}
__device__ __forceinline__ u64 pk2(float a, float b) {
    u64 r; asm("mov.b64 %0, {%1, %2};" : "=l"(r) : "f"(a), "f"(b)); return r;
}
__device__ __forceinline__ void upk2(float& a, float& b, u64 v) {
    asm("mov.b64 {%0, %1}, %2;" : "=f"(a), "=f"(b) : "l"(v));
}
__device__ __forceinline__ u64 add2(u64 a, u64 b) {
    u64 r; asm("add.rn.f32x2 %0, %1, %2;" : "=l"(r) : "l"(a), "l"(b)); return r;
}
__device__ __forceinline__ u64 mul2(u64 a, u64 b) {
    u64 r; asm("mul.rn.f32x2 %0, %1, %2;" : "=l"(r) : "l"(a), "l"(b)); return r;
}
__device__ __forceinline__ u64 fma2(u64 a, u64 b, u64 c) {
    u64 r; asm("fma.rn.f32x2 %0, %1, %2, %3;" : "=l"(r) : "l"(a), "l"(b), "l"(c)); return r;
}

__global__ __launch_bounds__(TPB, 2)
void yolino_main(const float* __restrict__ target, const float* __restrict__ pred,
                 float* __restrict__ out)
{
    const int n = blockIdx.x * TPB + threadIdx.x;   // n in [0, NCELL)
    const int w  = n % GW;
    const int t1 = n / GW;
    const int h  = t1 % GH;
    const int b  = t1 / GH;

    const float* tb = target + (size_t)b * 64 * HW + (size_t)h * GW + w;
    const float* pb = pred   + (size_t)b * 96 * HW + (size_t)h * GW + w;

    // Load all 16 target lines (4 coords each) — coalesced across the warp.
    float tlv[LN][4];
    #pragma unroll
    for (int l = 0; l < LN; ++l) {
        #pragma unroll
        for (int j = 0; j < 4; ++j)
            tlv[l][j] = tb[(size_t)(l * 4 + j) * HW];
    }

    // Valid-line mask: sum of the 4 coords > 0
    unsigned tmask = 0;
    #pragma unroll
    for (int l = 0; l < LN; ++l) {
        float s = (tlv[l][0] + tlv[l][1]) + (tlv[l][2] + tlv[l][3]);
        if (s > 0.f) tmask |= (1u << l);
    }

    // Repack target lines as f32x2 pairs: (l even, l odd) per coordinate.
    u64 tp[LN / 2][4];
    #pragma unroll
    for (int lp = 0; lp < LN / 2; ++lp) {
        #pragma unroll
        for (int j = 0; j < 4; ++j)
            tp[lp][j] = pk2(tlv[2 * lp][j], tlv[2 * lp + 1][j]);
    }

    float loss = 0.f;

    // Prefetch predictor 0's six channels.
    float q0 = pb[0], q1 = pb[HW], q2 = pb[2 * HW],
          q3 = pb[3 * HW], q4 = pb[4 * HW], q5 = pb[5 * HW];

    #pragma unroll 1
    for (int p = 0; p < PN; ++p) {
        const float c0 = q0, c1 = q1, c2 = q2, c3 = q3, c4 = q4, c5 = q5;

        // Prefetch next predictor while we crunch this one.
        if (p + 1 < PN) {
            const float* nb = pb + (size_t)((p + 1) * 6) * HW;
            q0 = nb[0];      q1 = nb[HW];     q2 = nb[2 * HW];
            q3 = nb[3 * HW]; q4 = nb[4 * HW]; q5 = nb[5 * HW];
        }

        // Broadcast negated predictor endpoints (so dx = t + (-c) via add.f32x2)
        const u64 n0 = pk2(-c0, -c0), n1 = pk2(-c1, -c1),
                  n2 = pk2(-c2, -c2), n3 = pk2(-c3, -c3);

        float d[LN];
        float m = 3.4e38f;
        #pragma unroll
        for (int lp = 0; lp < LN / 2; ++lp) {
            u64 dx1 = add2(tp[lp][0], n0);
            u64 dy1 = add2(tp[lp][1], n1);
            u64 dx2 = add2(tp[lp][2], n2);
            u64 dy2 = add2(tp[lp][3], n3);
            u64 s1 = fma2(dx1, dx1, mul2(dy1, dy1));
            u64 s2 = fma2(dx2, dx2, mul2(dy2, dy2));
            float a0, a1, b0, b1;
            upk2(a0, a1, s1);
            upk2(b0, b1, s2);
            float d0 = asqrt(a0) + asqrt(b0);
            float d1 = asqrt(a1) + asqrt(b1);
            d[2 * lp]     = d0;
            d[2 * lp + 1] = d1;
            m = fminf(m, fminf(d0, d1));
        }

        const float thr = (m < 2.f) ? m : -1.f;

        float cnt  = 0.f;   // number of l with ijk_mask true for this p
        float dsum = 0.f;   // sum of dist over selected l
        #pragma unroll
        for (int l = 0; l < LN; ++l) {
            bool sel = (d[l] == thr) && ((tmask >> l) & 1u);
            if (sel) { dsum += d[l]; cnt += 1.f; }
        }
        loss += dsum;

        // Confidence term: (sig-1)^2 if any match else sig^2
        float sig = 1.f / (1.f + __expf(-c4));
        float e   = (cnt > 0.f) ? (sig - 1.f) : sig;
        loss = fmaf(e, e, loss);

        // Class term: (1 - cls_hard)^2 summed over selected l.
        // cls_hard = sigmoid(c5) > 0.5  <=>  c5 > 0
        if (!(c5 > 0.f)) loss += cnt;
    }

    // ---- block reduction (deterministic) ----
    #pragma unroll
    for (int o = 16; o > 0; o >>= 1)
        loss += __shfl_xor_sync(0xffffffffu, loss, o);

    __shared__ float sw[TPB / 32];
    __shared__ bool  s_last;
    const int lane = threadIdx.x & 31;
    const int wid  = threadIdx.x >> 5;
    if (lane == 0) sw[wid] = loss;
    __syncthreads();
    if (wid == 0) {
        float v = (lane < TPB / 32) ? sw[lane] : 0.f;
        #pragma unroll
        for (int o = 4; o > 0; o >>= 1)
            v += __shfl_xor_sync(0xffffffffu, v, o);
        if (lane == 0) {
            g_partials[blockIdx.x] = v;
            __threadfence();
            unsigned t = atomicAdd(&g_ticket, 1u);
            s_last = (t == NBLK - 1);
        }
    }
    __syncthreads();

    // ---- last block folds all partials into the output ----
    if (s_last) {
        __threadfence();  // acquire: make all g_partials visible
        const int t = threadIdx.x;
        float v = g_partials[t];
        if (t + 256 < NBLK) v += g_partials[t + 256];
        __shared__ float s[256];
        s[t] = v;
        __syncthreads();
        #pragma unroll
        for (int o = 128; o > 0; o >>= 1) {
            if (t < o) s[t] += s[t + o];
            __syncthreads();
        }
        if (t == 0) {
            out[0] = s[0] * (1.0f / BSZ);
            g_ticket = 0;   // reset for the next (graph-replayed) launch
        }
    }
}

extern "C" void kernel_launch(void* const* d_in, const int* in_sizes, int n_in,
                              void* d_out, int out_size)
{
    const float* target = (const float*)d_in[0];
    const float* pred   = (const float*)d_in[1];
    float* out = (float*)d_out;

    yolino_main<<<NBLK, TPB>>>(target, pred, out);
}